// round 1
// baseline (speedup 1.0000x reference)
#include <cuda_runtime.h>
#include <math.h>

// Problem constants
#define D_MODEL 1024
#define NHEAD   16
#define HD      64
#define SEQ     2048
#define BATCH   2
#define NTOK    (BATCH * SEQ)          // 4096
#define QKV_LD  (3 * D_MODEL)          // 3072

// Scratch (no cudaMalloc allowed) — lives in HBM, ~64 MB total
__device__ float g_qkv[(size_t)NTOK * QKV_LD];   // [4096, 3072] row-major, col = h*192 + c
__device__ float g_att[(size_t)NTOK * D_MODEL];  // [4096, 1024] row-major, col = h*64 + d

// ---------------------------------------------------------------------------
// Tiled SGEMM with bias: C[M,N] = A[M,K] @ B[K,N] + bias[N]
// Block tile 128x128, K-step 8, 256 threads, 8x8 per-thread microtile.
// M,N divisible by 128; K divisible by 8 (true for all calls here).
// ---------------------------------------------------------------------------
__global__ __launch_bounds__(256) void sgemm_bias_kernel(
    const float* __restrict__ A, const float* __restrict__ B,
    const float* __restrict__ bias, float* __restrict__ C,
    int M, int N, int K)
{
    __shared__ float As[8][128];
    __shared__ float Bs[8][128];

    const int tid  = threadIdx.x;
    const int row0 = blockIdx.y * 128;
    const int col0 = blockIdx.x * 128;

    const int tr = (tid / 16) * 8;   // 0..120 row in tile
    const int tc = (tid % 16) * 8;   // 0..120 col in tile

    // A tile load mapping: 128 rows x 8 k, one float4 per thread
    const int arow = tid >> 1;          // 0..127
    const int acol = (tid & 1) * 4;     // 0 or 4
    // B tile load mapping: 8 k-rows x 128 cols, one float4 per thread
    const int brow = tid >> 5;          // 0..7
    const int bcol = (tid & 31) * 4;    // 0..124

    const float* Aptr = A + (size_t)(row0 + arow) * K + acol;
    const float* Bptr = B + (size_t)brow * N + col0 + bcol;

    float acc[8][8];
#pragma unroll
    for (int i = 0; i < 8; i++)
#pragma unroll
        for (int j = 0; j < 8; j++) acc[i][j] = 0.f;

    for (int k0 = 0; k0 < K; k0 += 8) {
        float4 av = *(const float4*)(Aptr + k0);
        As[acol + 0][arow] = av.x;
        As[acol + 1][arow] = av.y;
        As[acol + 2][arow] = av.z;
        As[acol + 3][arow] = av.w;
        float4 bv = *(const float4*)(Bptr + (size_t)k0 * N);
        *(float4*)&Bs[brow][bcol] = bv;
        __syncthreads();

#pragma unroll
        for (int kk = 0; kk < 8; kk++) {
            float a[8], b[8];
            *(float4*)&a[0] = *(const float4*)&As[kk][tr];
            *(float4*)&a[4] = *(const float4*)&As[kk][tr + 4];
            *(float4*)&b[0] = *(const float4*)&Bs[kk][tc];
            *(float4*)&b[4] = *(const float4*)&Bs[kk][tc + 4];
#pragma unroll
            for (int i = 0; i < 8; i++)
#pragma unroll
                for (int j = 0; j < 8; j++)
                    acc[i][j] += a[i] * b[j];
        }
        __syncthreads();
    }

    // Epilogue: add bias, store
#pragma unroll
    for (int i = 0; i < 8; i++) {
        const size_t r = (size_t)(row0 + tr + i);
#pragma unroll
        for (int j4 = 0; j4 < 2; j4++) {
            const int c = col0 + tc + 4 * j4;
            float4 v;
            v.x = acc[i][4 * j4 + 0] + bias[c + 0];
            v.y = acc[i][4 * j4 + 1] + bias[c + 1];
            v.z = acc[i][4 * j4 + 2] + bias[c + 2];
            v.w = acc[i][4 * j4 + 3] + bias[c + 3];
            *(float4*)&C[r * N + c] = v;
        }
    }
}

// ---------------------------------------------------------------------------
// Flash-style attention, fp32. One thread = one query row; block = 128
// queries of one (b, h). K/V streamed through smem in 64-key tiles,
// scores computed in 8-key chunks (keeps regs + I$ bounded).
// q/o/accumulators live in registers (hd = 64).
// ---------------------------------------------------------------------------
__global__ __launch_bounds__(128) void attn_kernel()
{
    const int b = blockIdx.z;
    const int h = blockIdx.y;
    const int qi = blockIdx.x * 128 + threadIdx.x;   // 0..2047
    const size_t t = (size_t)b * SEQ + qi;

    __shared__ float Ks[64][64];
    __shared__ float Vs[64][64];

    float q[HD], o[HD];
    const float* qptr = g_qkv + t * QKV_LD + h * (3 * HD);
#pragma unroll
    for (int d4 = 0; d4 < 16; d4++) {
        float4 v = *(const float4*)(qptr + 4 * d4);
        q[4 * d4 + 0] = v.x * 0.125f;   // 1/sqrt(64)
        q[4 * d4 + 1] = v.y * 0.125f;
        q[4 * d4 + 2] = v.z * 0.125f;
        q[4 * d4 + 3] = v.w * 0.125f;
    }
#pragma unroll
    for (int d = 0; d < HD; d++) o[d] = 0.f;

    float m = -INFINITY;
    float l = 0.f;

    for (int s0 = 0; s0 < SEQ; s0 += 64) {
        // Cooperative load of K and V tiles (64 keys x 64 dims each)
        const float* kvbase = g_qkv + ((size_t)b * SEQ + s0) * QKV_LD + h * (3 * HD) + HD;
        for (int i = threadIdx.x; i < 64 * 16; i += 128) {
            const int r  = i >> 4;
            const int c4 = (i & 15) * 4;
            const float* rowp = kvbase + (size_t)r * QKV_LD;
            *(float4*)&Ks[r][c4] = *(const float4*)(rowp + c4);        // K
            *(float4*)&Vs[r][c4] = *(const float4*)(rowp + HD + c4);   // V
        }
        __syncthreads();

#pragma unroll 1
        for (int c = 0; c < 64; c += 8) {
            float s[8];
#pragma unroll
            for (int j = 0; j < 8; j++) {
                float acc = 0.f;
#pragma unroll
                for (int d4 = 0; d4 < 16; d4++) {
                    float4 kv = *(const float4*)&Ks[c + j][4 * d4];
                    acc += q[4 * d4 + 0] * kv.x;
                    acc += q[4 * d4 + 1] * kv.y;
                    acc += q[4 * d4 + 2] * kv.z;
                    acc += q[4 * d4 + 3] * kv.w;
                }
                s[j] = acc;
            }
            float cm = s[0];
#pragma unroll
            for (int j = 1; j < 8; j++) cm = fmaxf(cm, s[j]);
            const float mn = fmaxf(m, cm);
            const float alpha = __expf(m - mn);
            m = mn;
            l *= alpha;
#pragma unroll
            for (int d = 0; d < HD; d++) o[d] *= alpha;
#pragma unroll
            for (int j = 0; j < 8; j++) {
                const float p = __expf(s[j] - mn);
                l += p;
#pragma unroll
                for (int d4 = 0; d4 < 16; d4++) {
                    float4 vv = *(const float4*)&Vs[c + j][4 * d4];
                    o[4 * d4 + 0] += p * vv.x;
                    o[4 * d4 + 1] += p * vv.y;
                    o[4 * d4 + 2] += p * vv.z;
                    o[4 * d4 + 3] += p * vv.w;
                }
            }
        }
        __syncthreads();
    }

    const float inv = 1.f / l;
    float* optr = g_att + t * D_MODEL + h * HD;
#pragma unroll
    for (int d4 = 0; d4 < 16; d4++) {
        float4 v;
        v.x = o[4 * d4 + 0] * inv;
        v.y = o[4 * d4 + 1] * inv;
        v.z = o[4 * d4 + 2] * inv;
        v.w = o[4 * d4 + 3] * inv;
        *(float4*)&optr[4 * d4] = v;
    }
}

// ---------------------------------------------------------------------------
// kernel_launch: qkv GEMM -> attention -> out GEMM. Graph-capturable:
// only kernel launches + symbol-address queries, no allocs, no syncs.
// ---------------------------------------------------------------------------
extern "C" void kernel_launch(void* const* d_in, const int* in_sizes, int n_in,
                              void* d_out, int out_size)
{
    const float* x    = (const float*)d_in[0];   // [2, 2048, 1024]
    const float* Wqkv = (const float*)d_in[1];   // [1024, 3072]
    const float* bqkv = (const float*)d_in[2];   // [3072]
    const float* Wout = (const float*)d_in[3];   // [1024, 1024]
    const float* bout = (const float*)d_in[4];   // [1024]
    float* out = (float*)d_out;                  // [2, 2048, 1024]

    float* qkvbuf = nullptr;
    float* attbuf = nullptr;
    cudaGetSymbolAddress((void**)&qkvbuf, g_qkv);
    cudaGetSymbolAddress((void**)&attbuf, g_att);

    // 1) qkv = x @ Wqkv + bqkv    [4096, 3072]
    {
        dim3 grid(QKV_LD / 128, NTOK / 128);   // (24, 32)
        sgemm_bias_kernel<<<grid, 256>>>(x, Wqkv, bqkv, qkvbuf,
                                         NTOK, QKV_LD, D_MODEL);
    }

    // 2) attention per (b, h), 128 queries per block
    {
        dim3 grid(SEQ / 128, NHEAD, BATCH);    // (16, 16, 2)
        attn_kernel<<<grid, 128>>>();
    }

    // 3) out = att @ Wout + bout  [4096, 1024]
    {
        dim3 grid(D_MODEL / 128, NTOK / 128);  // (8, 32)
        sgemm_bias_kernel<<<grid, 256>>>(attbuf, Wout, bout, out,
                                         NTOK, D_MODEL, D_MODEL);
    }
}

// round 2
// speedup vs baseline: 3.3768x; 3.3768x over previous
#include <cuda_runtime.h>
#include <math.h>

// Problem constants
#define D_MODEL 1024
#define NHEAD   16
#define HD      64
#define SEQ     2048
#define BATCH   2
#define NTOK    (BATCH * SEQ)          // 4096
#define QKV_LD  (3 * D_MODEL)          // 3072

// HBM scratch (no cudaMalloc allowed)
__device__ float g_qkv[(size_t)NTOK * QKV_LD];   // [4096, 3072]
__device__ float g_att[(size_t)NTOK * D_MODEL];  // [4096, 1024]

// ---------------------------------------------------------------------------
// helpers: tf32 convert + m16n8k8 tf32 mma
// ---------------------------------------------------------------------------
__device__ __forceinline__ unsigned f2tf(float f) {
    unsigned u;
    asm("cvt.rna.tf32.f32 %0, %1;" : "=r"(u) : "f"(f));
    return u;
}
__device__ __forceinline__ float f2tf_f(float f) {
    return __uint_as_float(f2tf(f));
}
__device__ __forceinline__ void mma_tf32(float c[4], const unsigned a[4],
                                         unsigned b0, unsigned b1) {
    asm volatile(
        "mma.sync.aligned.m16n8k8.row.col.f32.tf32.tf32.f32 "
        "{%0,%1,%2,%3}, {%4,%5,%6,%7}, {%8,%9}, {%0,%1,%2,%3};"
        : "+f"(c[0]), "+f"(c[1]), "+f"(c[2]), "+f"(c[3])
        : "r"(a[0]), "r"(a[1]), "r"(a[2]), "r"(a[3]), "r"(b0), "r"(b1));
}

// ---------------------------------------------------------------------------
// TF32 tensor-core GEMM with bias: C[M,N] = A[M,K] @ B[K,N] + bias[N]
// 128x128 block, 8 warps (32m x 64n each), K-step 16, double-buffered smem.
// As stored transposed [k][m] stride 136 (frag loads bank-conflict-free).
// Bs stored [k][n] stride 136.
// ---------------------------------------------------------------------------
#define GSTR 136
__global__ __launch_bounds__(256) void gemm_tf32_kernel(
    const float* __restrict__ A, const float* __restrict__ B,
    const float* __restrict__ bias, float* __restrict__ C,
    int M, int N, int K)
{
    __shared__ float As[2][16 * GSTR];
    __shared__ float Bs[2][16 * GSTR];

    const int tid  = threadIdx.x;
    const int lane = tid & 31;
    const int warp = tid >> 5;
    const int row0 = blockIdx.y * 128;
    const int col0 = blockIdx.x * 128;
    const int wm = (warp & 3) * 32;     // warp row offset in tile
    const int wn = (warp >> 2) * 64;    // warp col offset in tile

    // gmem load mapping
    const int ar  = tid >> 2;           // 0..63 (+64)
    const int ak4 = (tid & 3) * 4;      // 0,4,8,12
    const int bk  = tid >> 5;           // 0..7 (+8)
    const int bn4 = (tid & 31) * 4;     // 0..124

    const float* Ap = A + (size_t)(row0 + ar) * K + ak4;
    const float* Bp = B + (size_t)bk * N + col0 + bn4;

    float acc[2][8][4];
#pragma unroll
    for (int mf = 0; mf < 2; mf++)
#pragma unroll
        for (int nf = 0; nf < 8; nf++)
#pragma unroll
            for (int x = 0; x < 4; x++) acc[mf][nf][x] = 0.f;

    const int nk = K / 16;
    float4 a0v, a1v, b0v, b1v;

    // prologue: load tile 0
    a0v = *(const float4*)(Ap);
    a1v = *(const float4*)(Ap + (size_t)64 * K);
    b0v = *(const float4*)(Bp);
    b1v = *(const float4*)(Bp + (size_t)8 * N);
    {
        float* As0 = As[0];
        As0[(ak4 + 0) * GSTR + ar] = f2tf_f(a0v.x);
        As0[(ak4 + 1) * GSTR + ar] = f2tf_f(a0v.y);
        As0[(ak4 + 2) * GSTR + ar] = f2tf_f(a0v.z);
        As0[(ak4 + 3) * GSTR + ar] = f2tf_f(a0v.w);
        As0[(ak4 + 0) * GSTR + ar + 64] = f2tf_f(a1v.x);
        As0[(ak4 + 1) * GSTR + ar + 64] = f2tf_f(a1v.y);
        As0[(ak4 + 2) * GSTR + ar + 64] = f2tf_f(a1v.z);
        As0[(ak4 + 3) * GSTR + ar + 64] = f2tf_f(a1v.w);
        float4 c0 = make_float4(f2tf_f(b0v.x), f2tf_f(b0v.y), f2tf_f(b0v.z), f2tf_f(b0v.w));
        float4 c1 = make_float4(f2tf_f(b1v.x), f2tf_f(b1v.y), f2tf_f(b1v.z), f2tf_f(b1v.w));
        *(float4*)&Bs[0][bk * GSTR + bn4] = c0;
        *(float4*)&Bs[0][(bk + 8) * GSTR + bn4] = c1;
    }
    __syncthreads();

    int cur = 0;
    for (int kb = 0; kb < nk; kb++) {
        const bool has_next = (kb + 1) < nk;
        if (has_next) {
            const int k0 = (kb + 1) * 16;
            a0v = *(const float4*)(Ap + k0);
            a1v = *(const float4*)(Ap + (size_t)64 * K + k0);
            b0v = *(const float4*)(Bp + (size_t)k0 * N);
            b1v = *(const float4*)(Bp + (size_t)(k0 + 8) * N);
        }

        const float* Ac = As[cur];
        const float* Bc = Bs[cur];
#pragma unroll
        for (int ks = 0; ks < 2; ks++) {
            unsigned af[2][4];
#pragma unroll
            for (int mf = 0; mf < 2; mf++) {
                const int m = wm + mf * 16 + (lane >> 2);
                const int k = ks * 8 + (lane & 3);
                af[mf][0] = __float_as_uint(Ac[k * GSTR + m]);
                af[mf][1] = __float_as_uint(Ac[k * GSTR + m + 8]);
                af[mf][2] = __float_as_uint(Ac[(k + 4) * GSTR + m]);
                af[mf][3] = __float_as_uint(Ac[(k + 4) * GSTR + m + 8]);
            }
#pragma unroll
            for (int nf = 0; nf < 8; nf++) {
                const int n = wn + nf * 8 + (lane >> 2);
                const int k = ks * 8 + (lane & 3);
                unsigned b0 = __float_as_uint(Bc[k * GSTR + n]);
                unsigned b1 = __float_as_uint(Bc[(k + 4) * GSTR + n]);
                mma_tf32(acc[0][nf], af[0], b0, b1);
                mma_tf32(acc[1][nf], af[1], b0, b1);
            }
        }

        if (has_next) {
            float* An = As[cur ^ 1];
            float* Bn = Bs[cur ^ 1];
            An[(ak4 + 0) * GSTR + ar] = f2tf_f(a0v.x);
            An[(ak4 + 1) * GSTR + ar] = f2tf_f(a0v.y);
            An[(ak4 + 2) * GSTR + ar] = f2tf_f(a0v.z);
            An[(ak4 + 3) * GSTR + ar] = f2tf_f(a0v.w);
            An[(ak4 + 0) * GSTR + ar + 64] = f2tf_f(a1v.x);
            An[(ak4 + 1) * GSTR + ar + 64] = f2tf_f(a1v.y);
            An[(ak4 + 2) * GSTR + ar + 64] = f2tf_f(a1v.z);
            An[(ak4 + 3) * GSTR + ar + 64] = f2tf_f(a1v.w);
            float4 c0 = make_float4(f2tf_f(b0v.x), f2tf_f(b0v.y), f2tf_f(b0v.z), f2tf_f(b0v.w));
            float4 c1 = make_float4(f2tf_f(b1v.x), f2tf_f(b1v.y), f2tf_f(b1v.z), f2tf_f(b1v.w));
            *(float4*)&Bn[bk * GSTR + bn4] = c0;
            *(float4*)&Bn[(bk + 8) * GSTR + bn4] = c1;
        }
        __syncthreads();
        cur ^= 1;
    }

    // epilogue
#pragma unroll
    for (int mf = 0; mf < 2; mf++) {
#pragma unroll
        for (int nf = 0; nf < 8; nf++) {
            const int r = row0 + wm + mf * 16 + (lane >> 2);
            const int c = col0 + wn + nf * 8 + 2 * (lane & 3);
            const float bx = bias[c], by = bias[c + 1];
            float2 v0 = make_float2(acc[mf][nf][0] + bx, acc[mf][nf][1] + by);
            float2 v1 = make_float2(acc[mf][nf][2] + bx, acc[mf][nf][3] + by);
            *(float2*)&C[(size_t)r * N + c] = v0;
            *(float2*)&C[(size_t)(r + 8) * N + c] = v1;
        }
    }
}

// ---------------------------------------------------------------------------
// FlashAttention-2 style tf32 mma attention.
// Block: 256 thr = 8 warps, 128 queries. Warp w owns rows [w*16, w*16+16).
// Q frags register-resident. K/V tiles (64 keys) in smem. Online softmax on
// C-frags with intra-quad shuffles. P staged per-warp in smem (frag reshape).
// ---------------------------------------------------------------------------
#define KSTR 68
#define VSTR 72
#define PSTR 68
// smem float offsets
#define OFF_K 0
#define OFF_V (64 * KSTR)                 // 4352
#define OFF_P (OFF_V + 64 * VSTR)         // 8960
#define ATT_SMEM_FLOATS (OFF_P + 8 * 16 * PSTR)   // 17664 floats = 70656 B

__global__ __launch_bounds__(256) void attn_mma_kernel()
{
    extern __shared__ float sm[];
    const int tid  = threadIdx.x;
    const int lane = tid & 31;
    const int warp = tid >> 5;
    const int b  = blockIdx.z;
    const int h  = blockIdx.y;
    const int q0 = blockIdx.x * 128;
    const int r4 = lane >> 2;   // 0..7
    const int c4 = lane & 3;    // 0..3

    float* Ps = sm + OFF_P + warp * (16 * PSTR);

    // ---- Stage Q (scaled, tf32) into smem [128][KSTR], grab frags ----
    {
        const float* qb = g_qkv + ((size_t)b * SEQ + q0) * QKV_LD + h * (3 * HD);
        for (int i = tid; i < 128 * 16; i += 256) {
            const int r = i >> 4;
            const int cc = (i & 15) * 4;
            float4 v = *(const float4*)(qb + (size_t)r * QKV_LD + cc);
            sm[r * KSTR + cc + 0] = f2tf_f(v.x * 0.125f);
            sm[r * KSTR + cc + 1] = f2tf_f(v.y * 0.125f);
            sm[r * KSTR + cc + 2] = f2tf_f(v.z * 0.125f);
            sm[r * KSTR + cc + 3] = f2tf_f(v.w * 0.125f);
        }
    }
    __syncthreads();

    unsigned qf[8][4];
    {
        const int m = warp * 16 + r4;
#pragma unroll
        for (int kk = 0; kk < 8; kk++) {
            const int k = kk * 8 + c4;
            qf[kk][0] = __float_as_uint(sm[m * KSTR + k]);
            qf[kk][1] = __float_as_uint(sm[(m + 8) * KSTR + k]);
            qf[kk][2] = __float_as_uint(sm[m * KSTR + k + 4]);
            qf[kk][3] = __float_as_uint(sm[(m + 8) * KSTR + k + 4]);
        }
    }
    __syncthreads();   // Q staging area will be overwritten by K/V

    float oacc[8][4];
#pragma unroll
    for (int j = 0; j < 8; j++)
#pragma unroll
        for (int x = 0; x < 4; x++) oacc[j][x] = 0.f;
    float mrow[2] = {-INFINITY, -INFINITY};
    float lrow[2] = {0.f, 0.f};

    for (int s0 = 0; s0 < SEQ; s0 += 64) {
        // ---- load K,V tiles (tf32) ----
        const float* kvb = g_qkv + ((size_t)b * SEQ + s0) * QKV_LD + h * (3 * HD) + HD;
        for (int i = tid; i < 64 * 16; i += 256) {
            const int r = i >> 4;
            const int cc = (i & 15) * 4;
            const float* rp = kvb + (size_t)r * QKV_LD;
            float4 kv = *(const float4*)(rp + cc);
            float4 vv = *(const float4*)(rp + HD + cc);
            sm[OFF_K + r * KSTR + cc + 0] = f2tf_f(kv.x);
            sm[OFF_K + r * KSTR + cc + 1] = f2tf_f(kv.y);
            sm[OFF_K + r * KSTR + cc + 2] = f2tf_f(kv.z);
            sm[OFF_K + r * KSTR + cc + 3] = f2tf_f(kv.w);
            sm[OFF_V + r * VSTR + cc + 0] = f2tf_f(vv.x);
            sm[OFF_V + r * VSTR + cc + 1] = f2tf_f(vv.y);
            sm[OFF_V + r * VSTR + cc + 2] = f2tf_f(vv.z);
            sm[OFF_V + r * VSTR + cc + 3] = f2tf_f(vv.w);
        }
        __syncthreads();

        // ---- S = Q @ K^T : sacc[j][4], j = key octet ----
        float sacc[8][4];
#pragma unroll
        for (int j = 0; j < 8; j++) {
            sacc[j][0] = sacc[j][1] = sacc[j][2] = sacc[j][3] = 0.f;
#pragma unroll
            for (int kk = 0; kk < 8; kk++) {
                const int key = j * 8 + r4;
                const int d = kk * 8 + c4;
                unsigned b0 = __float_as_uint(sm[OFF_K + key * KSTR + d]);
                unsigned b1 = __float_as_uint(sm[OFF_K + key * KSTR + d + 4]);
                mma_tf32(sacc[j], qf[kk], b0, b1);
            }
        }

        // ---- online softmax ----
        float mA = sacc[0][0], mB = sacc[0][2];
#pragma unroll
        for (int j = 0; j < 8; j++) {
            mA = fmaxf(mA, fmaxf(sacc[j][0], sacc[j][1]));
            mB = fmaxf(mB, fmaxf(sacc[j][2], sacc[j][3]));
        }
        mA = fmaxf(mA, __shfl_xor_sync(0xffffffffu, mA, 1));
        mA = fmaxf(mA, __shfl_xor_sync(0xffffffffu, mA, 2));
        mB = fmaxf(mB, __shfl_xor_sync(0xffffffffu, mB, 1));
        mB = fmaxf(mB, __shfl_xor_sync(0xffffffffu, mB, 2));
        const float mnA = fmaxf(mrow[0], mA);
        const float mnB = fmaxf(mrow[1], mB);
        const float alA = __expf(mrow[0] - mnA);
        const float alB = __expf(mrow[1] - mnB);
        mrow[0] = mnA; mrow[1] = mnB;

        float sumA = 0.f, sumB = 0.f;
#pragma unroll
        for (int j = 0; j < 8; j++) {
            const float p0 = __expf(sacc[j][0] - mnA);
            const float p1 = __expf(sacc[j][1] - mnA);
            const float p2 = __expf(sacc[j][2] - mnB);
            const float p3 = __expf(sacc[j][3] - mnB);
            sumA += p0 + p1;
            sumB += p2 + p3;
            const int cc = j * 8 + 2 * c4;
            Ps[r4 * PSTR + cc]           = f2tf_f(p0);
            Ps[r4 * PSTR + cc + 1]       = f2tf_f(p1);
            Ps[(r4 + 8) * PSTR + cc]     = f2tf_f(p2);
            Ps[(r4 + 8) * PSTR + cc + 1] = f2tf_f(p3);
        }
        sumA += __shfl_xor_sync(0xffffffffu, sumA, 1);
        sumA += __shfl_xor_sync(0xffffffffu, sumA, 2);
        sumB += __shfl_xor_sync(0xffffffffu, sumB, 1);
        sumB += __shfl_xor_sync(0xffffffffu, sumB, 2);
        lrow[0] = lrow[0] * alA + sumA;
        lrow[1] = lrow[1] * alB + sumB;

#pragma unroll
        for (int j = 0; j < 8; j++) {
            oacc[j][0] *= alA; oacc[j][1] *= alA;
            oacc[j][2] *= alB; oacc[j][3] *= alB;
        }
        __syncwarp();

        // ---- O += P @ V ----
#pragma unroll
        for (int kk = 0; kk < 8; kk++) {
            unsigned af[4];
            const int k = kk * 8 + c4;
            af[0] = __float_as_uint(Ps[r4 * PSTR + k]);
            af[1] = __float_as_uint(Ps[(r4 + 8) * PSTR + k]);
            af[2] = __float_as_uint(Ps[r4 * PSTR + k + 4]);
            af[3] = __float_as_uint(Ps[(r4 + 8) * PSTR + k + 4]);
#pragma unroll
            for (int j = 0; j < 8; j++) {
                const int key = kk * 8 + c4;
                const int d = j * 8 + r4;
                unsigned b0 = __float_as_uint(sm[OFF_V + key * VSTR + d]);
                unsigned b1 = __float_as_uint(sm[OFF_V + (key + 4) * VSTR + d]);
                mma_tf32(oacc[j], af, b0, b1);
            }
        }
        __syncthreads();
    }

    // ---- epilogue: O /= l, store fp32 ----
    const float invA = 1.f / lrow[0];
    const float invB = 1.f / lrow[1];
    const size_t t = (size_t)b * SEQ + q0 + warp * 16 + r4;
    float* ob = g_att + t * D_MODEL + h * HD;
#pragma unroll
    for (int j = 0; j < 8; j++) {
        const int cc = j * 8 + 2 * c4;
        *(float2*)&ob[cc] = make_float2(oacc[j][0] * invA, oacc[j][1] * invA);
        *(float2*)&ob[8 * D_MODEL + cc] = make_float2(oacc[j][2] * invB, oacc[j][3] * invB);
    }
}

// ---------------------------------------------------------------------------
extern "C" void kernel_launch(void* const* d_in, const int* in_sizes, int n_in,
                              void* d_out, int out_size)
{
    const float* x    = (const float*)d_in[0];
    const float* Wqkv = (const float*)d_in[1];
    const float* bqkv = (const float*)d_in[2];
    const float* Wout = (const float*)d_in[3];
    const float* bout = (const float*)d_in[4];
    float* out = (float*)d_out;

    float* qkvbuf = nullptr;
    float* attbuf = nullptr;
    cudaGetSymbolAddress((void**)&qkvbuf, g_qkv);
    cudaGetSymbolAddress((void**)&attbuf, g_att);

    static bool attr_done = false;
    if (!attr_done) {
        cudaFuncSetAttribute(attn_mma_kernel,
                             cudaFuncAttributeMaxDynamicSharedMemorySize,
                             ATT_SMEM_FLOATS * (int)sizeof(float));
        attr_done = true;
    }

    // 1) qkv = x @ Wqkv + bqkv    [4096, 3072]
    {
        dim3 grid(QKV_LD / 128, NTOK / 128);   // (24, 32)
        gemm_tf32_kernel<<<grid, 256>>>(x, Wqkv, bqkv, qkvbuf,
                                        NTOK, QKV_LD, D_MODEL);
    }
    // 2) attention
    {
        dim3 grid(SEQ / 128, NHEAD, BATCH);    // (16, 16, 2)
        attn_mma_kernel<<<grid, 256, ATT_SMEM_FLOATS * (int)sizeof(float)>>>();
    }
    // 3) out = att @ Wout + bout  [4096, 1024]
    {
        dim3 grid(D_MODEL / 128, NTOK / 128);  // (8, 32)
        gemm_tf32_kernel<<<grid, 256>>>(attbuf, Wout, bout, out,
                                        NTOK, D_MODEL, D_MODEL);
    }
}